// round 17
// baseline (speedup 1.0000x reference)
#include <cuda_runtime.h>
#include <cuda_fp16.h>
#include <cstdint>

// VectorQuantizer: x:[128,1024,64] f32, embeddings:[64,1024] f32.
// score(f,k) = ||e_k||^2 - 2 f.e_k (||f||^2 per-row const); out = e_{argmin}.
//
// Tensor path: legacy mma.sync.m16n8k16 (tcgen05 gated off by the harness's
// compute_103 PTX target). fp16 2-way split, 3 terms: hh + hm + mh
// (mm dropped: rms ~4e-8). Measured HMMA floor ~85us; R16 hit it exactly
// (tensor 66.2% x 127.7us).
//
// R17: kill the wave tail. 1024 CTAs over 444 resident slots = waves
// 444/444/136 -> last wave runs the chip at ~30% occupancy. Replace with
// 444 PERSISTENT CTAs pulling row-blocks from a global atomic counter
// (reset in prep each launch -> deterministic + graph-capturable).
// Norms staged once per CTA (hoisted out of the work loop).

#define NUM_K  1024
#define DIM    64
#define N_ROWS (128 * 1024)
#define MROWS  128
#define NBLOCKS (N_ROWS / MROWS)   // 1024 work items
#define NT_CODES 32
#define NTILES (NUM_K / NT_CODES)  // 32
#define THREADS 128
#define GRID   444                 // 148 SMs x 3 CTAs/SM, one wave

__device__ __half g_eh[NUM_K * DIM];
__device__ __half g_em[NUM_K * DIM];
__device__ float g_norm2[NUM_K];
__device__ float g_embT[NUM_K * DIM];    // fp32 codebook [k][d] for gather
__device__ int   g_ctr;                  // work-stealing counter

// smem layout (bytes): 3-deep B ring + norms + block broadcast
#define SM_B     0                  // 3 bufs x (2 splits x 32 rows x 128B)
#define BUFB     8192
#define B_SUB    4096
#define SM_NORM  24576              // 1024 f32
#define SM_BLK   28672              // 1 int
#define DYN_SMEM 28688

static __device__ __forceinline__ uint32_t smem_u32(const void* p) {
    uint32_t a;
    asm("{ .reg .u64 t; cvta.to.shared.u64 t, %1; cvt.u32.u64 %0, t; }"
        : "=r"(a) : "l"(p));
    return a;
}
static __device__ __forceinline__ void cp_async16(uint32_t dst, const void* src) {
    asm volatile("cp.async.cg.shared.global [%0], [%1], 16;"
                 :: "r"(dst), "l"(src));
}
static __device__ __forceinline__ uint32_t pack_h(float2 v) {
    __half2 h(__float2half_rn(v.x), __float2half_rn(v.y));
    return *reinterpret_cast<uint32_t*>(&h);
}
static __device__ __forceinline__ uint32_t pack_m(float2 v) {
    __half hx = __float2half_rn(v.x), hy = __float2half_rn(v.y);
    __half2 m(__float2half_rn(v.x - __half2float(hx)),
              __float2half_rn(v.y - __half2float(hy)));
    return *reinterpret_cast<uint32_t*>(&m);
}

#define LDSM_X4(r0, r1, r2, r3, a) \
    asm volatile("ldmatrix.sync.aligned.m8n8.x4.shared.b16 {%0,%1,%2,%3}, [%4];" \
                 : "=r"(r0), "=r"(r1), "=r"(r2), "=r"(r3) : "r"(a))
#define MMA_F16(c0, c1, c2, c3, a0, a1, a2, a3, b0, b1) \
    asm volatile("mma.sync.aligned.m16n8k16.row.col.f32.f16.f16.f32 " \
                 "{%0,%1,%2,%3}, {%4,%5,%6,%7}, {%8,%9}, {%0,%1,%2,%3};" \
                 : "+f"(c0), "+f"(c1), "+f"(c2), "+f"(c3) \
                 : "r"(a0), "r"(a1), "r"(a2), "r"(a3), "r"(b0), "r"(b1))

// ---------------------------------------------------------------------------
// Prep: transpose + fp16 split; threads < 1024 also compute code norms.
// Thread 0 resets the work-stealing counter for this launch.
// ---------------------------------------------------------------------------
__global__ void vq_prep_kernel(const float* __restrict__ emb) {
    int i = blockIdx.x * blockDim.x + threadIdx.x;   // 65536 elements
    if (i == 0) g_ctr = 0;
    int d = i >> 10, k = i & 1023;
    float v = emb[i];
    __half h = __float2half_rn(v);
    __half m = __float2half_rn(v - __half2float(h));
    g_embT[k * DIM + d] = v;
    g_eh[k * DIM + d] = h;
    g_em[k * DIM + d] = m;
    if (i < NUM_K) {
        float acc = 0.f;
#pragma unroll
        for (int dd = 0; dd < DIM; dd++) {
            float w = emb[dd * NUM_K + i];
            acc = fmaf(w, w, acc);
        }
        g_norm2[i] = acc;
    }
}

// ---------------------------------------------------------------------------
__global__ void __launch_bounds__(THREADS, 3)
vq_main_kernel(const float* __restrict__ x, float* __restrict__ out) {
    extern __shared__ char smem[];
    const uint32_t sb = smem_u32(smem);
    const int tid = threadIdx.x;
    const int lane = tid & 31;
    const int wid = tid >> 5;

    // Stage B tile nt (32 codes x 64 dims x 2 splits) into ring buffer buf.
    auto stageB = [&](int nt, int buf) {
        const int base = nt * NT_CODES * DIM;
#pragma unroll
        for (int s = 0; s < 2; s++) {
            const __half* g = (s == 0) ? g_eh : g_em;
#pragma unroll
            for (int i = 0; i < 2; i++) {
                int q = tid + THREADS * i;          // 16B chunk 0..255
                int row = q >> 3, ch = q & 7;
                uint32_t dst = sb + SM_B + buf * BUFB + s * B_SUB +
                               row * 128 + ((ch ^ (row & 7)) << 4);
                cp_async16(dst, reinterpret_cast<const char*>(g + base) + q * 16);
            }
        }
    };

    // Per-CTA once: stage all norms.
    float* snorm = reinterpret_cast<float*>(smem + SM_NORM);
#pragma unroll
    for (int i = 0; i < NUM_K / THREADS; i++)
        snorm[tid + THREADS * i] = g_norm2[tid + THREADS * i];
    int* sblk = reinterpret_cast<int*>(smem + SM_BLK);

    for (;;) {
        // Pull next row-block (barrier also orders prior block's smem reads).
        if (tid == 0) *sblk = atomicAdd(&g_ctr, 1);
        __syncthreads();
        const int blk = *sblk;
        if (blk >= NBLOCKS) break;

        // Prologue staging for this block's pass over the codebook.
        stageB(0, 0);
        asm volatile("cp.async.commit_group;");
        stageB(1, 1);
        asm volatile("cp.async.commit_group;");

        // A fragments in registers, built from gmem at the exact m16n8k16
        // positions: a0=(r,k) a1=(r+8,k) a2=(r,k+8) a3=(r+8,k+8),
        // r=lane>>2, k=2*(lane&3)+16*ks.
        uint32_t af[2][2][4][4];   // [split][mt][ks][reg]
        {
            const float* xb = x + (size_t)blk * MROWS * DIM;
            const int c2 = (lane & 3) * 2;
#pragma unroll
            for (int mt = 0; mt < 2; mt++) {
                const int r0 = wid * 32 + mt * 16 + (lane >> 2);
#pragma unroll
                for (int ks = 0; ks < 4; ks++) {
                    float2 v0 = *reinterpret_cast<const float2*>(
                        xb + (size_t)r0 * DIM + 16 * ks + c2);
                    float2 v1 = *reinterpret_cast<const float2*>(
                        xb + (size_t)(r0 + 8) * DIM + 16 * ks + c2);
                    float2 v2 = *reinterpret_cast<const float2*>(
                        xb + (size_t)r0 * DIM + 16 * ks + 8 + c2);
                    float2 v3 = *reinterpret_cast<const float2*>(
                        xb + (size_t)(r0 + 8) * DIM + 16 * ks + 8 + c2);
                    af[0][mt][ks][0] = pack_h(v0);
                    af[0][mt][ks][1] = pack_h(v1);
                    af[0][mt][ks][2] = pack_h(v2);
                    af[0][mt][ks][3] = pack_h(v3);
                    af[1][mt][ks][0] = pack_m(v0);
                    af[1][mt][ks][1] = pack_m(v1);
                    af[1][mt][ks][2] = pack_m(v2);
                    af[1][mt][ks][3] = pack_m(v3);
                }
            }
        }

        float best[4];
        int bidx[4];
#pragma unroll
        for (int s = 0; s < 4; s++) {
            best[s] = __int_as_float(0x7f800000);
            bidx[s] = 0;
        }

        for (int nt = 0; nt < NTILES; nt++) {
            const int cur = nt % 3;
            if (nt == NTILES - 1) {
                asm volatile("cp.async.wait_group 0;");
            } else {
                asm volatile("cp.async.wait_group 1;");
            }
            __syncthreads();   // copies visible; prior readers of reused buf done
            if (nt + 2 < NTILES) {
                stageB(nt + 2, (nt + 2) % 3);
                asm volatile("cp.async.commit_group;");
            }

            float cc[2][4][4];
#pragma unroll
            for (int mt = 0; mt < 2; mt++)
#pragma unroll
                for (int n8 = 0; n8 < 4; n8++)
#pragma unroll
                    for (int j = 0; j < 4; j++) cc[mt][n8][j] = 0.f;

#pragma unroll
            for (int ks = 0; ks < 4; ks++) {
#pragma unroll
                for (int np = 0; np < 2; np++) {
                    int n = 16 * np + ((lane >> 4) << 3) + (lane & 7);
                    int ch = 2 * ks + ((lane >> 3) & 1);
                    uint32_t boff = n * 128 + ((ch ^ (lane & 7)) << 4);
                    uint32_t b[2][4];
#pragma unroll
                    for (int sp = 0; sp < 2; sp++)
                        LDSM_X4(b[sp][0], b[sp][1], b[sp][2], b[sp][3],
                                sb + SM_B + cur * BUFB + sp * B_SUB + boff);
                    const int TA[3] = {0, 0, 1};
                    const int TB[3] = {0, 1, 0};
#pragma unroll
                    for (int tm = 0; tm < 3; tm++)
#pragma unroll
                        for (int mt = 0; mt < 2; mt++) {
                            MMA_F16(cc[mt][2 * np][0], cc[mt][2 * np][1],
                                    cc[mt][2 * np][2], cc[mt][2 * np][3],
                                    af[TA[tm]][mt][ks][0], af[TA[tm]][mt][ks][1],
                                    af[TA[tm]][mt][ks][2], af[TA[tm]][mt][ks][3],
                                    b[TB[tm]][0], b[TB[tm]][1]);
                            MMA_F16(cc[mt][2 * np + 1][0], cc[mt][2 * np + 1][1],
                                    cc[mt][2 * np + 1][2], cc[mt][2 * np + 1][3],
                                    af[TA[tm]][mt][ks][0], af[TA[tm]][mt][ks][1],
                                    af[TA[tm]][mt][ks][2], af[TA[tm]][mt][ks][3],
                                    b[TB[tm]][2], b[TB[tm]][3]);
                        }
                }
            }

            // Fused epilogue: score = norm2 - 2*dot, running argmin.
#pragma unroll
            for (int n8 = 0; n8 < 4; n8++) {
                int col = nt * NT_CODES + n8 * 8 + (lane & 3) * 2;
                float sn0 = snorm[col], sn1 = snorm[col + 1];
#pragma unroll
                for (int mt = 0; mt < 2; mt++) {
                    float s00 = fmaf(-2.f, cc[mt][n8][0], sn0);
                    float s01 = fmaf(-2.f, cc[mt][n8][1], sn1);
                    float s10 = fmaf(-2.f, cc[mt][n8][2], sn0);
                    float s11 = fmaf(-2.f, cc[mt][n8][3], sn1);
                    int s = mt * 2;
                    if (s00 < best[s]) { best[s] = s00; bidx[s] = col; }
                    if (s01 < best[s]) { best[s] = s01; bidx[s] = col + 1; }
                    if (s10 < best[s + 1]) { best[s + 1] = s10; bidx[s + 1] = col; }
                    if (s11 < best[s + 1]) { best[s + 1] = s11; bidx[s + 1] = col + 1; }
                }
            }
            // (next iteration's top barrier orders buffer reuse)
        }

        // Quad reduce (lanes sharing a row), lowest-index tiebreak.
#pragma unroll
        for (int s = 0; s < 4; s++) {
#pragma unroll
            for (int off = 1; off <= 2; off <<= 1) {
                float ob = __shfl_xor_sync(0xffffffffu, best[s], off);
                int oi = __shfl_xor_sync(0xffffffffu, bidx[s], off);
                if (ob < best[s] || (ob == best[s] && oi < bidx[s])) {
                    best[s] = ob;
                    bidx[s] = oi;
                }
            }
        }

        __syncthreads();   // mainloop smem reads done before sidx overlay
        int* sidx = reinterpret_cast<int*>(smem + SM_B);
        if ((lane & 3) == 0) {
#pragma unroll
            for (int s = 0; s < 4; s++) {
                int row = wid * 32 + (s >> 1) * 16 + (lane >> 2) + (s & 1) * 8;
                sidx[row] = bidx[s];
            }
        }
        __syncthreads();

        // Gather winning fp32 codebook row; thread tid = query row tid.
        {
            int k = sidx[tid];
            const float4* e =
                reinterpret_cast<const float4*>(g_embT + (size_t)k * DIM);
            float4* o = reinterpret_cast<float4*>(
                out + ((size_t)blk * MROWS + tid) * DIM);
#pragma unroll
            for (int i = 0; i < DIM / 4; i++) o[i] = e[i];
        }
        // loop-top barrier orders sidx reads before next block's staging
    }
}

extern "C" void kernel_launch(void* const* d_in, const int* in_sizes, int n_in,
                              void* d_out, int out_size) {
    const float* x   = (const float*)d_in[0];   // [128,1024,64] f32
    const float* emb = (const float*)d_in[1];   // [64,1024] f32
    float* out = (float*)d_out;

    cudaFuncSetAttribute(vq_main_kernel,
                         cudaFuncAttributeMaxDynamicSharedMemorySize, DYN_SMEM);

    vq_prep_kernel<<<(NUM_K * DIM) / 256, 256>>>(emb);
    vq_main_kernel<<<GRID, THREADS, DYN_SMEM>>>(x, out);
}